// round 8
// baseline (speedup 1.0000x reference)
#include <cuda_runtime.h>
#include <cuda_fp16.h>
#include <math.h>
#include <stdint.h>

#define NNODES 100000
#define NEDGES 1600000

// packed f32x2 FMA: d = a*b + d (elementwise on 2 packed fp32)
#define FMA2(d, a, b) \
    asm("fma.rn.f32x2 %0, %1, %2, %0;" : "+l"(d) : "l"(a), "l"(b))

__device__ __forceinline__ float f2lo(unsigned long long v) {
    return __uint_as_float((unsigned)(v & 0xffffffffull));
}
__device__ __forceinline__ float f2hi(unsigned long long v) {
    return __uint_as_float((unsigned)(v >> 32));
}
__device__ __forceinline__ unsigned long long packf2(float lo, float hi) {
    return (unsigned long long)__float_as_uint(lo) |
           ((unsigned long long)__float_as_uint(hi) << 32);
}
__device__ __forceinline__ float lrelu(float x) {
    return x > 0.f ? x : 0.2f * x;
}

// ---------------- scratch (device globals) ----------------
__device__ __align__(128) float  g_feat[NNODES * 128];
__device__ __align__(128) __half g_hh[NNODES * 128];   // fp16 H for layers 0/1
__device__ __align__(128) float  g_h[NNODES * 32];     // fp32 H for layer 2
__device__ float g_als[NNODES * 4];
__device__ float g_ald[NNODES * 4];
__device__ int   g_deg[NNODES];
__device__ int   g_off[NNODES + 1];
__device__ int   g_cur[NNODES];
__device__ int   g_bsum[128];
__device__ int   g_csr[NEDGES];

// ---------------- CSR build ----------------
__global__ void zero_deg_kernel(int n) {
    int i = blockIdx.x * blockDim.x + threadIdx.x;
    if (i < n) g_deg[i] = 0;
}
__global__ void count_kernel(const int* __restrict__ ei, int e) {
    int i = blockIdx.x * blockDim.x + threadIdx.x;
    if (i < e) atomicAdd(&g_deg[ei[e + i]], 1);
}
__global__ void scan1_kernel(int n) {
    __shared__ int sm[1024];
    int i = blockIdx.x * 1024 + threadIdx.x;
    int v = (i < n) ? g_deg[i] : 0;
    sm[threadIdx.x] = v;
    __syncthreads();
    #pragma unroll
    for (int d = 1; d < 1024; d <<= 1) {
        int t = (threadIdx.x >= d) ? sm[threadIdx.x - d] : 0;
        __syncthreads();
        sm[threadIdx.x] += t;
        __syncthreads();
    }
    if (i < n) g_off[i] = sm[threadIdx.x] - v;
    if (threadIdx.x == 1023) g_bsum[blockIdx.x] = sm[1023];
}
__global__ void scan2_kernel(int nb) {
    __shared__ int sm[128];
    int t = threadIdx.x;
    int v = (t < nb) ? g_bsum[t] : 0;
    sm[t] = v;
    __syncthreads();
    #pragma unroll
    for (int d = 1; d < 128; d <<= 1) {
        int tv = (t >= d) ? sm[t - d] : 0;
        __syncthreads();
        sm[t] += tv;
        __syncthreads();
    }
    if (t < nb) g_bsum[t] = sm[t] - v;
}
__global__ void scan3_kernel(int n, int e) {
    int i = blockIdx.x * 1024 + threadIdx.x;
    if (i < n) {
        int o = g_off[i] + g_bsum[blockIdx.x];
        g_off[i] = o;
        g_cur[i] = o;
    }
    if (i == 0) g_off[n] = e;
}
__global__ void fill_kernel(const int* __restrict__ ei, int e) {
    int i = blockIdx.x * blockDim.x + threadIdx.x;
    if (i < e) {
        int src = ei[i];
        int dst = ei[e + i];
        int pos = atomicAdd(&g_cur[dst], 1);
        g_csr[pos] = src;
    }
}

// ---------------- GEMM 128->128 (packed f32x2, conflict-free W) -> fp16 H ----------
__global__ __launch_bounds__(256, 2) void gemm128_kernel(
    const float4* __restrict__ A4, const float* __restrict__ W,
    const float* __restrict__ asrc, const float* __restrict__ adst,
    __half2* __restrict__ Hh, float* __restrict__ als, float* __restrict__ ald, int n)
{
    extern __shared__ char smc[];
    ulonglong2* Wq2 = (ulonglong2*)smc;            // 4096 * 16B = 64KB
    float4* Asm4 = (float4*)(smc + 65536);         // 2048 float4 = 32KB
    int tid = threadIdx.x;

    #pragma unroll 4
    for (int i = tid; i < 4096; i += 256) {
        int k2 = i >> 6;
        int half_ = (i >> 5) & 1;
        int l = i & 31;
        int c0 = 2 * l + 64 * half_;
        float w00 = W[(2 * k2) * 128 + c0];
        float w10 = W[(2 * k2 + 1) * 128 + c0];
        float w01 = W[(2 * k2) * 128 + c0 + 1];
        float w11 = W[(2 * k2 + 1) * 128 + c0 + 1];
        ulonglong2 p;
        p.x = packf2(w00, w10);
        p.y = packf2(w01, w11);
        Wq2[i] = p;
    }
    int rowbase = blockIdx.x * 64;
    #pragma unroll 2
    for (int i = tid; i < 2048; i += 256) {
        int row = rowbase + (i >> 5);
        Asm4[i] = (row < n) ? A4[(size_t)row * 32 + (i & 31)]
                            : make_float4(0.f, 0.f, 0.f, 0.f);
    }
    __syncthreads();

    int w = tid >> 5, lane = tid & 31;
    unsigned long long acc[8][4];
    #pragma unroll
    for (int r = 0; r < 8; r++)
        #pragma unroll
        for (int c = 0; c < 4; c++) acc[r][c] = 0ull;

    #pragma unroll 2
    for (int k4 = 0; k4 < 32; k4++) {
        ulonglong2 wa0 = Wq2[((2 * k4) * 2 + 0) * 32 + lane];
        ulonglong2 wb0 = Wq2[((2 * k4) * 2 + 1) * 32 + lane];
        ulonglong2 wa1 = Wq2[((2 * k4 + 1) * 2 + 0) * 32 + lane];
        ulonglong2 wb1 = Wq2[((2 * k4 + 1) * 2 + 1) * 32 + lane];
        #pragma unroll
        for (int r = 0; r < 8; r++) {
            ulonglong2 ap = *(const ulonglong2*)&Asm4[(w * 8 + r) * 32 + k4];
            FMA2(acc[r][0], ap.x, wa0.x);
            FMA2(acc[r][1], ap.x, wa0.y);
            FMA2(acc[r][2], ap.x, wb0.x);
            FMA2(acc[r][3], ap.x, wb0.y);
            FMA2(acc[r][0], ap.y, wa1.x);
            FMA2(acc[r][1], ap.y, wa1.y);
            FMA2(acc[r][2], ap.y, wb1.x);
            FMA2(acc[r][3], ap.y, wb1.y);
        }
    }

    // epilogue: cols {2L,2L+1} (head hA = lane>>4) and {2L+64,2L+65} (head hA+2)
    int c0 = 2 * lane;
    float as0 = asrc[c0], as1 = asrc[c0 + 1], as2_ = asrc[c0 + 64], as3 = asrc[c0 + 65];
    float ad0 = adst[c0], ad1 = adst[c0 + 1], ad2_ = adst[c0 + 64], ad3 = adst[c0 + 65];
    int hA = lane >> 4;
    #pragma unroll
    for (int r = 0; r < 8; r++) {
        int row = rowbase + w * 8 + r;
        if (row >= n) break;
        float v0 = f2lo(acc[r][0]) + f2hi(acc[r][0]);
        float v1 = f2lo(acc[r][1]) + f2hi(acc[r][1]);
        float v2 = f2lo(acc[r][2]) + f2hi(acc[r][2]);
        float v3 = f2lo(acc[r][3]) + f2hi(acc[r][3]);
        Hh[(size_t)row * 64 + lane] = __floats2half2_rn(v0, v1);
        Hh[(size_t)row * 64 + 32 + lane] = __floats2half2_rn(v2, v3);
        float psl = v0 * as0 + v1 * as1;
        float psh = v2 * as2_ + v3 * as3;
        float pdl = v0 * ad0 + v1 * ad1;
        float pdh = v2 * ad2_ + v3 * ad3;
        #pragma unroll
        for (int o = 1; o < 16; o <<= 1) {
            psl += __shfl_xor_sync(0xffffffffu, psl, o);
            psh += __shfl_xor_sync(0xffffffffu, psh, o);
            pdl += __shfl_xor_sync(0xffffffffu, pdl, o);
            pdh += __shfl_xor_sync(0xffffffffu, pdh, o);
        }
        if ((lane & 15) == 0) {
            als[row * 4 + hA] = psl;
            als[row * 4 + hA + 2] = psh;
            ald[row * 4 + hA] = pdl;
            ald[row * 4 + hA + 2] = pdh;
        }
    }
}

// ---------------- GEMM 128->32 (packed f32x2) + fused logits (1 head) --------------
__global__ __launch_bounds__(256) void gemm32_kernel(
    const float4* __restrict__ A4, const float* __restrict__ W,
    const float* __restrict__ asrc, const float* __restrict__ adst,
    float* __restrict__ H, float* __restrict__ als, float* __restrict__ ald, int n)
{
    __shared__ unsigned long long Wp[64 * 32];   // 16KB, lane-contiguous
    __shared__ float4 Asm4[2048];                // 32KB
    int tid = threadIdx.x;
    #pragma unroll 2
    for (int i = tid; i < 2048; i += 256) {
        int k2 = i >> 5, l = i & 31;
        Wp[i] = packf2(W[(k2 * 2) * 32 + l], W[(k2 * 2 + 1) * 32 + l]);
    }
    int rowbase = blockIdx.x * 64;
    #pragma unroll 2
    for (int i = tid; i < 2048; i += 256) {
        int row = rowbase + (i >> 5);
        Asm4[i] = (row < n) ? A4[(size_t)row * 32 + (i & 31)]
                            : make_float4(0.f, 0.f, 0.f, 0.f);
    }
    __syncthreads();

    int w = tid >> 5, lane = tid & 31;
    unsigned long long acc[8];
    #pragma unroll
    for (int r = 0; r < 8; r++) acc[r] = 0ull;

    #pragma unroll 4
    for (int k4 = 0; k4 < 32; k4++) {
        unsigned long long w0 = Wp[(2 * k4) * 32 + lane];
        unsigned long long w1 = Wp[(2 * k4 + 1) * 32 + lane];
        #pragma unroll
        for (int r = 0; r < 8; r++) {
            ulonglong2 ap = *(const ulonglong2*)&Asm4[(w * 8 + r) * 32 + k4];
            FMA2(acc[r], ap.x, w0);
            FMA2(acc[r], ap.y, w1);
        }
    }

    float asl = asrc[lane], adl = adst[lane];
    #pragma unroll
    for (int r = 0; r < 8; r++) {
        int row = rowbase + w * 8 + r;
        if (row >= n) break;
        float v = f2lo(acc[r]) + f2hi(acc[r]);
        H[(size_t)row * 32 + lane] = v;
        float ps = v * asl;
        float pd = v * adl;
        #pragma unroll
        for (int o = 1; o < 32; o <<= 1) {
            ps += __shfl_xor_sync(0xffffffffu, ps, o);
            pd += __shfl_xor_sync(0xffffffffu, pd, o);
        }
        if (lane == 0) { als[row] = ps; ald[row] = pd; }
    }
}

// ------- aggregation 4 heads x 32ch: batched index prefetch (8 edges/batch) --------
// Warp per node. One coalesced csr LDG fetches 8 indices; shfl-broadcast; all 16
// gathers (8 als + 8 H) issue before any consumption -> MLP 16, 2-level chain broken.
__global__ __launch_bounds__(256) void agg128_kernel(
    const uint2* __restrict__ Hh, const float* __restrict__ als,
    const float* __restrict__ ald,
    const float* __restrict__ bias, const float* __restrict__ gamma,
    const float* __restrict__ beta, const float* __restrict__ mean,
    const float* __restrict__ var,
    float4* __restrict__ out4, int n)
{
    int v = (blockIdx.x * blockDim.x + threadIdx.x) >> 5;
    if (v >= n) return;
    int lane = threadIdx.x & 31;
    int head = lane >> 3;
    float aldv = __ldg(&ald[v * 4 + head]);
    int s0 = g_off[v], s1 = g_off[v + 1];
    float s = 0.f;
    float4 acc = make_float4(0.f, 0.f, 0.f, 0.f);

    for (int base = s0; base < s1; base += 8) {
        int m = s1 - base;           // >= 1
        int myidx = base + (lane & 7);
        int uL = __ldg(&g_csr[(lane & 7) < m ? myidx : base]);
        int u[8];
        float e[8];
        uint2 p[8];
        #pragma unroll
        for (int j = 0; j < 8; j++) {
            u[j] = __shfl_sync(0xffffffffu, uL, j);
            e[j] = __ldg(&als[u[j] * 4 + head]);
            p[j] = __ldg(&Hh[(size_t)u[j] * 32 + lane]);
        }
        #pragma unroll
        for (int j = 0; j < 8; j++) {
            float wt = __expf(lrelu(e[j] + aldv));
            if (j >= m) wt = 0.f;
            s += wt;
            float2 a = __half22float2(*(__half2*)&p[j].x);
            float2 b = __half22float2(*(__half2*)&p[j].y);
            acc.x += wt * a.x;
            acc.y += wt * a.y;
            acc.z += wt * b.x;
            acc.w += wt * b.y;
        }
    }

    float inv = 1.f / (s + 1e-16f);
    float4 bi = ((const float4*)bias)[lane];
    float4 mn = ((const float4*)mean)[lane];
    float4 vr = ((const float4*)var)[lane];
    float4 gm = ((const float4*)gamma)[lane];
    float4 bt = ((const float4*)beta)[lane];
    float4 y;
    y.x = (acc.x * inv + bi.x - mn.x) * rsqrtf(vr.x + 1e-5f) * gm.x + bt.x;
    y.y = (acc.y * inv + bi.y - mn.y) * rsqrtf(vr.y + 1e-5f) * gm.y + bt.y;
    y.z = (acc.z * inv + bi.z - mn.z) * rsqrtf(vr.z + 1e-5f) * gm.z + bt.z;
    y.w = (acc.w * inv + bi.w - mn.w) * rsqrtf(vr.w + 1e-5f) * gm.w + bt.w;
    y.x = y.x > 0.f ? y.x : expm1f(y.x);
    y.y = y.y > 0.f ? y.y : expm1f(y.y);
    y.z = y.z > 0.f ? y.z : expm1f(y.z);
    y.w = y.w > 0.f ? y.w : expm1f(y.w);
    out4[(size_t)v * 32 + lane] = y;
}

// ------- layer-2 aggregation (1 head, fp32), batched prefetch + classifier ---------
__global__ __launch_bounds__(256) void agg32_kernel(
    const float* __restrict__ H, const float* __restrict__ als,
    const float* __restrict__ ald,
    const float* __restrict__ bias, const float* __restrict__ gamma,
    const float* __restrict__ beta, const float* __restrict__ mean,
    const float* __restrict__ var,
    const float* __restrict__ Wc, const float* __restrict__ bc,
    float* __restrict__ out, int n)
{
    int v = (blockIdx.x * blockDim.x + threadIdx.x) >> 5;
    if (v >= n) return;
    int lane = threadIdx.x & 31;
    float aldv = __ldg(&ald[v]);
    int s0 = g_off[v], s1 = g_off[v + 1];
    float s = 0.f, acc = 0.f;

    for (int base = s0; base < s1; base += 8) {
        int m = s1 - base;
        int myidx = base + (lane & 7);
        int uL = __ldg(&g_csr[(lane & 7) < m ? myidx : base]);
        int u[8];
        float e[8], h[8];
        #pragma unroll
        for (int j = 0; j < 8; j++) {
            u[j] = __shfl_sync(0xffffffffu, uL, j);
            e[j] = __ldg(&als[u[j]]);
            h[j] = __ldg(&H[(size_t)u[j] * 32 + lane]);
        }
        #pragma unroll
        for (int j = 0; j < 8; j++) {
            float wt = __expf(lrelu(e[j] + aldv));
            if (j >= m) wt = 0.f;
            s += wt;
            acc += wt * h[j];
        }
    }

    float y = acc / (s + 1e-16f) + bias[lane];
    y = (y - mean[lane]) * rsqrtf(var[lane] + 1e-5f) * gamma[lane] + beta[lane];
    y = y > 0.f ? y : expm1f(y);
    #pragma unroll
    for (int cc = 0; cc < 10; cc++) {
        float p = y * Wc[lane * 10 + cc];
        #pragma unroll
        for (int o = 16; o; o >>= 1) p += __shfl_xor_sync(0xffffffffu, p, o);
        if (lane == 0) out[(size_t)v * 10 + cc] = p + bc[cc];
    }
}

// ---------------- launch ----------------
extern "C" void kernel_launch(void* const* d_in, const int* in_sizes, int n_in,
                              void* d_out, int out_size) {
    const float* x   = (const float*)d_in[0];
    const int*   ei  = (const int*)d_in[1];
    const float* W0  = (const float*)d_in[2];
    const float* as0 = (const float*)d_in[3];
    const float* ad0 = (const float*)d_in[4];
    const float* b0  = (const float*)d_in[5];
    const float* gm0 = (const float*)d_in[6];
    const float* bt0 = (const float*)d_in[7];
    const float* m0  = (const float*)d_in[8];
    const float* v0  = (const float*)d_in[9];
    const float* W1  = (const float*)d_in[10];
    const float* as1 = (const float*)d_in[11];
    const float* ad1 = (const float*)d_in[12];
    const float* b1  = (const float*)d_in[13];
    const float* gm1 = (const float*)d_in[14];
    const float* bt1 = (const float*)d_in[15];
    const float* m1  = (const float*)d_in[16];
    const float* v1  = (const float*)d_in[17];
    const float* W2  = (const float*)d_in[18];
    const float* as2 = (const float*)d_in[19];
    const float* ad2 = (const float*)d_in[20];
    const float* b2  = (const float*)d_in[21];
    const float* gm2 = (const float*)d_in[22];
    const float* bt2 = (const float*)d_in[23];
    const float* m2  = (const float*)d_in[24];
    const float* v2  = (const float*)d_in[25];
    const float* Wc  = (const float*)d_in[26];
    const float* bc  = (const float*)d_in[27];

    int n = in_sizes[0] / 128;   // 100000
    int e = in_sizes[1] / 2;     // 1600000

    float *feat, *h, *als, *ald;
    __half *hh;
    cudaGetSymbolAddress((void**)&feat, g_feat);
    cudaGetSymbolAddress((void**)&hh, g_hh);
    cudaGetSymbolAddress((void**)&h, g_h);
    cudaGetSymbolAddress((void**)&als, g_als);
    cudaGetSymbolAddress((void**)&ald, g_ald);

    cudaFuncSetAttribute(gemm128_kernel,
                         cudaFuncAttributeMaxDynamicSharedMemorySize, 96 * 1024);

    int nb = (n + 1023) / 1024;
    int eb = (e + 255) / 256;
    int gemm_blocks = (n + 63) / 64;
    int agg_blocks = (n + 7) / 8;

    // gemm128 kept at launch index 3 (ncu capture slot) as control
    zero_deg_kernel<<<(n + 255) / 256, 256>>>(n);
    count_kernel<<<eb, 256>>>(ei, e);
    scan1_kernel<<<nb, 1024>>>(n);
    gemm128_kernel<<<gemm_blocks, 256, 96 * 1024>>>(
        (const float4*)x, W0, as0, ad0, (__half2*)hh, als, ald, n);
    scan2_kernel<<<1, 128>>>(nb);
    scan3_kernel<<<nb, 1024>>>(n, e);
    fill_kernel<<<eb, 256>>>(ei, e);

    // layer 0 aggregation
    agg128_kernel<<<agg_blocks, 256>>>(
        (const uint2*)hh, als, ald, b0, gm0, bt0, m0, v0, (float4*)feat, n);

    // layer 1
    gemm128_kernel<<<gemm_blocks, 256, 96 * 1024>>>(
        (const float4*)feat, W1, as1, ad1, (__half2*)hh, als, ald, n);
    agg128_kernel<<<agg_blocks, 256>>>(
        (const uint2*)hh, als, ald, b1, gm1, bt1, m1, v1, (float4*)feat, n);

    // layer 2 (single head, fp32) + classifier
    gemm32_kernel<<<gemm_blocks, 256>>>(
        (const float4*)feat, W2, as2, ad2, h, als, ald, n);
    agg32_kernel<<<agg_blocks, 256>>>(
        h, als, ald, b2, gm2, bt2, m2, v2, Wc, bc, (float*)d_out, n);
}

// round 9
// speedup vs baseline: 1.0989x; 1.0989x over previous
#include <cuda_runtime.h>
#include <cuda_fp16.h>
#include <math.h>
#include <stdint.h>

#define NNODES 100000
#define NEDGES 1600000

// packed f32x2 FMA: d = a*b + d (elementwise on 2 packed fp32)
#define FMA2(d, a, b) \
    asm("fma.rn.f32x2 %0, %1, %2, %0;" : "+l"(d) : "l"(a), "l"(b))

__device__ __forceinline__ float f2lo(unsigned long long v) {
    return __uint_as_float((unsigned)(v & 0xffffffffull));
}
__device__ __forceinline__ float f2hi(unsigned long long v) {
    return __uint_as_float((unsigned)(v >> 32));
}
__device__ __forceinline__ unsigned long long packf2(float lo, float hi) {
    return (unsigned long long)__float_as_uint(lo) |
           ((unsigned long long)__float_as_uint(hi) << 32);
}
__device__ __forceinline__ float lrelu(float x) {
    return x > 0.f ? x : 0.2f * x;
}

// ---------------- scratch (device globals) ----------------
__device__ __align__(128) float  g_feat[NNODES * 128];
__device__ __align__(128) __half g_hh[NNODES * 128];   // fp16 H for layers 0/1
__device__ __align__(128) float  g_h[NNODES * 32];     // fp32 H for layer 2
__device__ float g_als[NNODES * 4];
__device__ float g_ald[NNODES * 4];
__device__ int   g_deg[NNODES];
__device__ int   g_off[NNODES + 1];
__device__ int   g_cur[NNODES];
__device__ int   g_bsum[128];
__device__ int   g_csr[NEDGES];

// ---------------- CSR build ----------------
__global__ void zero_deg_kernel(int n) {
    int i = blockIdx.x * blockDim.x + threadIdx.x;
    if (i < n) g_deg[i] = 0;
}
__global__ void count_kernel(const int* __restrict__ ei, int e) {
    int i = blockIdx.x * blockDim.x + threadIdx.x;
    if (i < e) atomicAdd(&g_deg[ei[e + i]], 1);
}
__global__ void scan1_kernel(int n) {
    __shared__ int sm[1024];
    int i = blockIdx.x * 1024 + threadIdx.x;
    int v = (i < n) ? g_deg[i] : 0;
    sm[threadIdx.x] = v;
    __syncthreads();
    #pragma unroll
    for (int d = 1; d < 1024; d <<= 1) {
        int t = (threadIdx.x >= d) ? sm[threadIdx.x - d] : 0;
        __syncthreads();
        sm[threadIdx.x] += t;
        __syncthreads();
    }
    if (i < n) g_off[i] = sm[threadIdx.x] - v;
    if (threadIdx.x == 1023) g_bsum[blockIdx.x] = sm[1023];
}
__global__ void scan2_kernel(int nb) {
    __shared__ int sm[128];
    int t = threadIdx.x;
    int v = (t < nb) ? g_bsum[t] : 0;
    sm[t] = v;
    __syncthreads();
    #pragma unroll
    for (int d = 1; d < 128; d <<= 1) {
        int tv = (t >= d) ? sm[t - d] : 0;
        __syncthreads();
        sm[t] += tv;
        __syncthreads();
    }
    if (t < nb) g_bsum[t] = sm[t] - v;
}
__global__ void scan3_kernel(int n, int e) {
    int i = blockIdx.x * 1024 + threadIdx.x;
    if (i < n) {
        int o = g_off[i] + g_bsum[blockIdx.x];
        g_off[i] = o;
        g_cur[i] = o;
    }
    if (i == 0) g_off[n] = e;
}
__global__ void fill_kernel(const int* __restrict__ ei, int e) {
    int i = blockIdx.x * blockDim.x + threadIdx.x;
    if (i < e) {
        int src = ei[i];
        int dst = ei[e + i];
        int pos = atomicAdd(&g_cur[dst], 1);
        g_csr[pos] = src;
    }
}

// ---------------- GEMM 128->128 (packed f32x2, conflict-free W) -> fp16 H ----------
__global__ __launch_bounds__(256, 2) void gemm128_kernel(
    const float4* __restrict__ A4, const float* __restrict__ W,
    const float* __restrict__ asrc, const float* __restrict__ adst,
    __half2* __restrict__ Hh, float* __restrict__ als, float* __restrict__ ald, int n)
{
    extern __shared__ char smc[];
    ulonglong2* Wq2 = (ulonglong2*)smc;            // 4096 * 16B = 64KB
    float4* Asm4 = (float4*)(smc + 65536);         // 2048 float4 = 32KB
    int tid = threadIdx.x;

    #pragma unroll 4
    for (int i = tid; i < 4096; i += 256) {
        int k2 = i >> 6;
        int half_ = (i >> 5) & 1;
        int l = i & 31;
        int c0 = 2 * l + 64 * half_;
        float w00 = W[(2 * k2) * 128 + c0];
        float w10 = W[(2 * k2 + 1) * 128 + c0];
        float w01 = W[(2 * k2) * 128 + c0 + 1];
        float w11 = W[(2 * k2 + 1) * 128 + c0 + 1];
        ulonglong2 p;
        p.x = packf2(w00, w10);
        p.y = packf2(w01, w11);
        Wq2[i] = p;
    }
    int rowbase = blockIdx.x * 64;
    #pragma unroll 2
    for (int i = tid; i < 2048; i += 256) {
        int row = rowbase + (i >> 5);
        Asm4[i] = (row < n) ? A4[(size_t)row * 32 + (i & 31)]
                            : make_float4(0.f, 0.f, 0.f, 0.f);
    }
    __syncthreads();

    int w = tid >> 5, lane = tid & 31;
    unsigned long long acc[8][4];
    #pragma unroll
    for (int r = 0; r < 8; r++)
        #pragma unroll
        for (int c = 0; c < 4; c++) acc[r][c] = 0ull;

    #pragma unroll 2
    for (int k4 = 0; k4 < 32; k4++) {
        ulonglong2 wa0 = Wq2[((2 * k4) * 2 + 0) * 32 + lane];
        ulonglong2 wb0 = Wq2[((2 * k4) * 2 + 1) * 32 + lane];
        ulonglong2 wa1 = Wq2[((2 * k4 + 1) * 2 + 0) * 32 + lane];
        ulonglong2 wb1 = Wq2[((2 * k4 + 1) * 2 + 1) * 32 + lane];
        #pragma unroll
        for (int r = 0; r < 8; r++) {
            ulonglong2 ap = *(const ulonglong2*)&Asm4[(w * 8 + r) * 32 + k4];
            FMA2(acc[r][0], ap.x, wa0.x);
            FMA2(acc[r][1], ap.x, wa0.y);
            FMA2(acc[r][2], ap.x, wb0.x);
            FMA2(acc[r][3], ap.x, wb0.y);
            FMA2(acc[r][0], ap.y, wa1.x);
            FMA2(acc[r][1], ap.y, wa1.y);
            FMA2(acc[r][2], ap.y, wb1.x);
            FMA2(acc[r][3], ap.y, wb1.y);
        }
    }

    // epilogue: cols {2L,2L+1} (head hA = lane>>4) and {2L+64,2L+65} (head hA+2)
    int c0 = 2 * lane;
    float as0 = asrc[c0], as1 = asrc[c0 + 1], as2_ = asrc[c0 + 64], as3 = asrc[c0 + 65];
    float ad0 = adst[c0], ad1 = adst[c0 + 1], ad2_ = adst[c0 + 64], ad3 = adst[c0 + 65];
    int hA = lane >> 4;
    #pragma unroll
    for (int r = 0; r < 8; r++) {
        int row = rowbase + w * 8 + r;
        if (row >= n) break;
        float v0 = f2lo(acc[r][0]) + f2hi(acc[r][0]);
        float v1 = f2lo(acc[r][1]) + f2hi(acc[r][1]);
        float v2 = f2lo(acc[r][2]) + f2hi(acc[r][2]);
        float v3 = f2lo(acc[r][3]) + f2hi(acc[r][3]);
        Hh[(size_t)row * 64 + lane] = __floats2half2_rn(v0, v1);
        Hh[(size_t)row * 64 + 32 + lane] = __floats2half2_rn(v2, v3);
        float psl = v0 * as0 + v1 * as1;
        float psh = v2 * as2_ + v3 * as3;
        float pdl = v0 * ad0 + v1 * ad1;
        float pdh = v2 * ad2_ + v3 * ad3;
        #pragma unroll
        for (int o = 1; o < 16; o <<= 1) {
            psl += __shfl_xor_sync(0xffffffffu, psl, o);
            psh += __shfl_xor_sync(0xffffffffu, psh, o);
            pdl += __shfl_xor_sync(0xffffffffu, pdl, o);
            pdh += __shfl_xor_sync(0xffffffffu, pdh, o);
        }
        if ((lane & 15) == 0) {
            als[row * 4 + hA] = psl;
            als[row * 4 + hA + 2] = psh;
            ald[row * 4 + hA] = pdl;
            ald[row * 4 + hA + 2] = pdh;
        }
    }
}

// ---------------- GEMM 128->32 (packed f32x2) + fused logits (1 head) --------------
__global__ __launch_bounds__(256) void gemm32_kernel(
    const float4* __restrict__ A4, const float* __restrict__ W,
    const float* __restrict__ asrc, const float* __restrict__ adst,
    float* __restrict__ H, float* __restrict__ als, float* __restrict__ ald, int n)
{
    __shared__ unsigned long long Wp[64 * 32];   // 16KB, lane-contiguous
    __shared__ float4 Asm4[2048];                // 32KB
    int tid = threadIdx.x;
    #pragma unroll 2
    for (int i = tid; i < 2048; i += 256) {
        int k2 = i >> 5, l = i & 31;
        Wp[i] = packf2(W[(k2 * 2) * 32 + l], W[(k2 * 2 + 1) * 32 + l]);
    }
    int rowbase = blockIdx.x * 64;
    #pragma unroll 2
    for (int i = tid; i < 2048; i += 256) {
        int row = rowbase + (i >> 5);
        Asm4[i] = (row < n) ? A4[(size_t)row * 32 + (i & 31)]
                            : make_float4(0.f, 0.f, 0.f, 0.f);
    }
    __syncthreads();

    int w = tid >> 5, lane = tid & 31;
    unsigned long long acc[8];
    #pragma unroll
    for (int r = 0; r < 8; r++) acc[r] = 0ull;

    #pragma unroll 4
    for (int k4 = 0; k4 < 32; k4++) {
        unsigned long long w0 = Wp[(2 * k4) * 32 + lane];
        unsigned long long w1 = Wp[(2 * k4 + 1) * 32 + lane];
        #pragma unroll
        for (int r = 0; r < 8; r++) {
            ulonglong2 ap = *(const ulonglong2*)&Asm4[(w * 8 + r) * 32 + k4];
            FMA2(acc[r], ap.x, w0);
            FMA2(acc[r], ap.y, w1);
        }
    }

    float asl = asrc[lane], adl = adst[lane];
    #pragma unroll
    for (int r = 0; r < 8; r++) {
        int row = rowbase + w * 8 + r;
        if (row >= n) break;
        float v = f2lo(acc[r]) + f2hi(acc[r]);
        H[(size_t)row * 32 + lane] = v;
        float ps = v * asl;
        float pd = v * adl;
        #pragma unroll
        for (int o = 1; o < 32; o <<= 1) {
            ps += __shfl_xor_sync(0xffffffffu, ps, o);
            pd += __shfl_xor_sync(0xffffffffu, pd, o);
        }
        if (lane == 0) { als[row] = ps; ald[row] = pd; }
    }
}

// ---------------- aggregation 4 heads x 32ch, fp16 H gathers, unroll-4 --------------
__global__ __launch_bounds__(256) void agg128_kernel(
    const uint2* __restrict__ Hh, const float* __restrict__ als,
    const float* __restrict__ ald,
    const float* __restrict__ bias, const float* __restrict__ gamma,
    const float* __restrict__ beta, const float* __restrict__ mean,
    const float* __restrict__ var,
    float4* __restrict__ out4, int n)
{
    int v = (blockIdx.x * blockDim.x + threadIdx.x) >> 5;
    if (v >= n) return;
    int lane = threadIdx.x & 31;
    int head = lane >> 3;
    float aldv = __ldg(&ald[v * 4 + head]);
    int s0 = g_off[v], s1 = g_off[v + 1];
    float s = 0.f;
    float4 acc = make_float4(0.f, 0.f, 0.f, 0.f);

    int idx = s0;
    for (; idx + 4 <= s1; idx += 4) {
        int u0 = __ldg(&g_csr[idx]);
        int u1 = __ldg(&g_csr[idx + 1]);
        int u2 = __ldg(&g_csr[idx + 2]);
        int u3 = __ldg(&g_csr[idx + 3]);
        float e0 = __ldg(&als[u0 * 4 + head]) + aldv;
        float e1 = __ldg(&als[u1 * 4 + head]) + aldv;
        float e2 = __ldg(&als[u2 * 4 + head]) + aldv;
        float e3 = __ldg(&als[u3 * 4 + head]) + aldv;
        uint2 p0 = __ldg(&Hh[(size_t)u0 * 32 + lane]);
        uint2 p1 = __ldg(&Hh[(size_t)u1 * 32 + lane]);
        uint2 p2 = __ldg(&Hh[(size_t)u2 * 32 + lane]);
        uint2 p3 = __ldg(&Hh[(size_t)u3 * 32 + lane]);
        float w0 = __expf(lrelu(e0));
        float w1 = __expf(lrelu(e1));
        float w2 = __expf(lrelu(e2));
        float w3 = __expf(lrelu(e3));
        s += (w0 + w1) + (w2 + w3);
        float2 a0 = __half22float2(*(__half2*)&p0.x), b0 = __half22float2(*(__half2*)&p0.y);
        float2 a1 = __half22float2(*(__half2*)&p1.x), b1 = __half22float2(*(__half2*)&p1.y);
        float2 a2 = __half22float2(*(__half2*)&p2.x), b2 = __half22float2(*(__half2*)&p2.y);
        float2 a3 = __half22float2(*(__half2*)&p3.x), b3 = __half22float2(*(__half2*)&p3.y);
        acc.x += w0 * a0.x + w1 * a1.x + w2 * a2.x + w3 * a3.x;
        acc.y += w0 * a0.y + w1 * a1.y + w2 * a2.y + w3 * a3.y;
        acc.z += w0 * b0.x + w1 * b1.x + w2 * b2.x + w3 * b3.x;
        acc.w += w0 * b0.y + w1 * b1.y + w2 * b2.y + w3 * b3.y;
    }
    for (; idx < s1; idx++) {
        int u = __ldg(&g_csr[idx]);
        float wt = __expf(lrelu(__ldg(&als[u * 4 + head]) + aldv));
        uint2 p = __ldg(&Hh[(size_t)u * 32 + lane]);
        float2 a = __half22float2(*(__half2*)&p.x), b = __half22float2(*(__half2*)&p.y);
        s += wt;
        acc.x += wt * a.x;
        acc.y += wt * a.y;
        acc.z += wt * b.x;
        acc.w += wt * b.y;
    }

    float inv = 1.f / (s + 1e-16f);
    float4 bi = ((const float4*)bias)[lane];
    float4 mn = ((const float4*)mean)[lane];
    float4 vr = ((const float4*)var)[lane];
    float4 gm = ((const float4*)gamma)[lane];
    float4 bt = ((const float4*)beta)[lane];
    float4 y;
    y.x = (acc.x * inv + bi.x - mn.x) * rsqrtf(vr.x + 1e-5f) * gm.x + bt.x;
    y.y = (acc.y * inv + bi.y - mn.y) * rsqrtf(vr.y + 1e-5f) * gm.y + bt.y;
    y.z = (acc.z * inv + bi.z - mn.z) * rsqrtf(vr.z + 1e-5f) * gm.z + bt.z;
    y.w = (acc.w * inv + bi.w - mn.w) * rsqrtf(vr.w + 1e-5f) * gm.w + bt.w;
    y.x = y.x > 0.f ? y.x : expm1f(y.x);
    y.y = y.y > 0.f ? y.y : expm1f(y.y);
    y.z = y.z > 0.f ? y.z : expm1f(y.z);
    y.w = y.w > 0.f ? y.w : expm1f(y.w);
    out4[(size_t)v * 32 + lane] = y;
}

// ---------------- layer-2 aggregation (1 head, fp32) + BN + ELU + classifier --------
__global__ __launch_bounds__(256) void agg32_kernel(
    const float* __restrict__ H, const float* __restrict__ als,
    const float* __restrict__ ald,
    const float* __restrict__ bias, const float* __restrict__ gamma,
    const float* __restrict__ beta, const float* __restrict__ mean,
    const float* __restrict__ var,
    const float* __restrict__ Wc, const float* __restrict__ bc,
    float* __restrict__ out, int n)
{
    int v = (blockIdx.x * blockDim.x + threadIdx.x) >> 5;
    if (v >= n) return;
    int lane = threadIdx.x & 31;
    float aldv = __ldg(&ald[v]);
    int s0 = g_off[v], s1 = g_off[v + 1];
    float s = 0.f, acc = 0.f;

    int idx = s0;
    for (; idx + 4 <= s1; idx += 4) {
        int u0 = __ldg(&g_csr[idx]);
        int u1 = __ldg(&g_csr[idx + 1]);
        int u2 = __ldg(&g_csr[idx + 2]);
        int u3 = __ldg(&g_csr[idx + 3]);
        float e0 = __ldg(&als[u0]) + aldv;
        float e1 = __ldg(&als[u1]) + aldv;
        float e2 = __ldg(&als[u2]) + aldv;
        float e3 = __ldg(&als[u3]) + aldv;
        float h0 = __ldg(&H[(size_t)u0 * 32 + lane]);
        float h1 = __ldg(&H[(size_t)u1 * 32 + lane]);
        float h2 = __ldg(&H[(size_t)u2 * 32 + lane]);
        float h3 = __ldg(&H[(size_t)u3 * 32 + lane]);
        float w0 = __expf(lrelu(e0));
        float w1 = __expf(lrelu(e1));
        float w2 = __expf(lrelu(e2));
        float w3 = __expf(lrelu(e3));
        s += (w0 + w1) + (w2 + w3);
        acc += w0 * h0 + w1 * h1 + w2 * h2 + w3 * h3;
    }
    for (; idx < s1; idx++) {
        int u = __ldg(&g_csr[idx]);
        float wt = __expf(lrelu(__ldg(&als[u]) + aldv));
        s += wt;
        acc += wt * __ldg(&H[(size_t)u * 32 + lane]);
    }

    float y = acc / (s + 1e-16f) + bias[lane];
    y = (y - mean[lane]) * rsqrtf(var[lane] + 1e-5f) * gamma[lane] + beta[lane];
    y = y > 0.f ? y : expm1f(y);
    #pragma unroll
    for (int cc = 0; cc < 10; cc++) {
        float p = y * Wc[lane * 10 + cc];
        #pragma unroll
        for (int o = 16; o; o >>= 1) p += __shfl_xor_sync(0xffffffffu, p, o);
        if (lane == 0) out[(size_t)v * 10 + cc] = p + bc[cc];
    }
}

// ---------------- launch ----------------
extern "C" void kernel_launch(void* const* d_in, const int* in_sizes, int n_in,
                              void* d_out, int out_size) {
    const float* x   = (const float*)d_in[0];
    const int*   ei  = (const int*)d_in[1];
    const float* W0  = (const float*)d_in[2];
    const float* as0 = (const float*)d_in[3];
    const float* ad0 = (const float*)d_in[4];
    const float* b0  = (const float*)d_in[5];
    const float* gm0 = (const float*)d_in[6];
    const float* bt0 = (const float*)d_in[7];
    const float* m0  = (const float*)d_in[8];
    const float* v0  = (const float*)d_in[9];
    const float* W1  = (const float*)d_in[10];
    const float* as1 = (const float*)d_in[11];
    const float* ad1 = (const float*)d_in[12];
    const float* b1  = (const float*)d_in[13];
    const float* gm1 = (const float*)d_in[14];
    const float* bt1 = (const float*)d_in[15];
    const float* m1  = (const float*)d_in[16];
    const float* v1  = (const float*)d_in[17];
    const float* W2  = (const float*)d_in[18];
    const float* as2 = (const float*)d_in[19];
    const float* ad2 = (const float*)d_in[20];
    const float* b2  = (const float*)d_in[21];
    const float* gm2 = (const float*)d_in[22];
    const float* bt2 = (const float*)d_in[23];
    const float* m2  = (const float*)d_in[24];
    const float* v2  = (const float*)d_in[25];
    const float* Wc  = (const float*)d_in[26];
    const float* bc  = (const float*)d_in[27];

    int n = in_sizes[0] / 128;   // 100000
    int e = in_sizes[1] / 2;     // 1600000

    float *feat, *h, *als, *ald;
    __half *hh;
    cudaGetSymbolAddress((void**)&feat, g_feat);
    cudaGetSymbolAddress((void**)&hh, g_hh);
    cudaGetSymbolAddress((void**)&h, g_h);
    cudaGetSymbolAddress((void**)&als, g_als);
    cudaGetSymbolAddress((void**)&ald, g_ald);

    cudaFuncSetAttribute(gemm128_kernel,
                         cudaFuncAttributeMaxDynamicSharedMemorySize, 96 * 1024);

    // side stream + fork/join events (created once; host-side resources only)
    static cudaStream_t s2 = nullptr;
    static cudaEvent_t evFork = nullptr, evCsr = nullptr;
    if (!s2) {
        cudaStreamCreateWithFlags(&s2, cudaStreamNonBlocking);
        cudaEventCreateWithFlags(&evFork, cudaEventDisableTiming);
        cudaEventCreateWithFlags(&evCsr, cudaEventDisableTiming);
    }

    int nb = (n + 1023) / 1024;
    int eb = (e + 255) / 256;
    int gemm_blocks = (n + 63) / 64;
    int agg_blocks = (n + 7) / 8;

    // fork: CSR build on s2, overlapped with layer-0 GEMM on the main stream
    cudaEventRecord(evFork, 0);
    cudaStreamWaitEvent(s2, evFork, 0);

    zero_deg_kernel<<<(n + 255) / 256, 256, 0, s2>>>(n);
    count_kernel<<<eb, 256, 0, s2>>>(ei, e);
    scan1_kernel<<<nb, 1024, 0, s2>>>(n);
    scan2_kernel<<<1, 128, 0, s2>>>(nb);
    scan3_kernel<<<nb, 1024, 0, s2>>>(n, e);
    fill_kernel<<<eb, 256, 0, s2>>>(ei, e);
    cudaEventRecord(evCsr, s2);

    // layer-0 GEMM on main stream (no CSR dependency)
    gemm128_kernel<<<gemm_blocks, 256, 96 * 1024>>>(
        (const float4*)x, W0, as0, ad0, (__half2*)hh, als, ald, n);

    // join: aggregation needs both the GEMM and the CSR
    cudaStreamWaitEvent(0, evCsr, 0);

    // layer 0 aggregation
    agg128_kernel<<<agg_blocks, 256>>>(
        (const uint2*)hh, als, ald, b0, gm0, bt0, m0, v0, (float4*)feat, n);

    // layer 1
    gemm128_kernel<<<gemm_blocks, 256, 96 * 1024>>>(
        (const float4*)feat, W1, as1, ad1, (__half2*)hh, als, ald, n);
    agg128_kernel<<<agg_blocks, 256>>>(
        (const uint2*)hh, als, ald, b1, gm1, bt1, m1, v1, (float4*)feat, n);

    // layer 2 (single head, fp32) + classifier
    gemm32_kernel<<<gemm_blocks, 256>>>(
        (const float4*)feat, W2, as2, ad2, h, als, ald, n);
    agg32_kernel<<<agg_blocks, 256>>>(
        h, als, ald, b2, gm2, bt2, m2, v2, Wc, bc, (float*)d_out, n);
}

// round 10
// speedup vs baseline: 1.1206x; 1.0198x over previous
#include <cuda_runtime.h>
#include <cuda_fp16.h>
#include <math.h>
#include <stdint.h>

#define NNODES 100000
#define NEDGES 1600000

// packed f32x2 FMA: d = a*b + d (elementwise on 2 packed fp32)
#define FMA2(d, a, b) \
    asm("fma.rn.f32x2 %0, %1, %2, %0;" : "+l"(d) : "l"(a), "l"(b))

__device__ __forceinline__ float f2lo(unsigned long long v) {
    return __uint_as_float((unsigned)(v & 0xffffffffull));
}
__device__ __forceinline__ float f2hi(unsigned long long v) {
    return __uint_as_float((unsigned)(v >> 32));
}
__device__ __forceinline__ unsigned long long packf2(float lo, float hi) {
    return (unsigned long long)__float_as_uint(lo) |
           ((unsigned long long)__float_as_uint(hi) << 32);
}
__device__ __forceinline__ float lrelu(float x) {
    return x > 0.f ? x : 0.2f * x;
}

// ---------------- scratch (device globals) ----------------
__device__ __align__(128) float  g_feat[NNODES * 128];
__device__ __align__(128) __half g_hh[NNODES * 128];   // fp16 H for layers 0/1
__device__ __align__(128) __half g_h2[NNODES * 32];    // fp16 H for layer 2
__device__ __align__(128) ulonglong2 g_Wp0[4096];      // prepacked W0 (64KB)
__device__ __align__(128) ulonglong2 g_Wp1[4096];      // prepacked W1 (64KB)
__device__ float g_als[NNODES * 4];
__device__ float g_ald[NNODES * 4];
__device__ int   g_deg[NNODES];
__device__ int   g_off[NNODES + 1];
__device__ int   g_cur[NNODES];
__device__ int   g_bsum[128];
__device__ int   g_csr[NEDGES];

// ---------------- CSR build ----------------
__global__ void zero_deg_kernel(int n) {
    int i = blockIdx.x * blockDim.x + threadIdx.x;
    if (i < n) g_deg[i] = 0;
}
__global__ void count_kernel(const int* __restrict__ ei, int e) {
    int i = blockIdx.x * blockDim.x + threadIdx.x;
    if (i < e) atomicAdd(&g_deg[ei[e + i]], 1);
}
__global__ void scan1_kernel(int n) {
    __shared__ int sm[1024];
    int i = blockIdx.x * 1024 + threadIdx.x;
    int v = (i < n) ? g_deg[i] : 0;
    sm[threadIdx.x] = v;
    __syncthreads();
    #pragma unroll
    for (int d = 1; d < 1024; d <<= 1) {
        int t = (threadIdx.x >= d) ? sm[threadIdx.x - d] : 0;
        __syncthreads();
        sm[threadIdx.x] += t;
        __syncthreads();
    }
    if (i < n) g_off[i] = sm[threadIdx.x] - v;
    if (threadIdx.x == 1023) g_bsum[blockIdx.x] = sm[1023];
}
__global__ void scan2_kernel(int nb) {
    __shared__ int sm[128];
    int t = threadIdx.x;
    int v = (t < nb) ? g_bsum[t] : 0;
    sm[t] = v;
    __syncthreads();
    #pragma unroll
    for (int d = 1; d < 128; d <<= 1) {
        int tv = (t >= d) ? sm[t - d] : 0;
        __syncthreads();
        sm[t] += tv;
        __syncthreads();
    }
    if (t < nb) g_bsum[t] = sm[t] - v;
}
__global__ void scan3_kernel(int n, int e) {
    int i = blockIdx.x * 1024 + threadIdx.x;
    if (i < n) {
        int o = g_off[i] + g_bsum[blockIdx.x];
        g_off[i] = o;
        g_cur[i] = o;
    }
    if (i == 0) g_off[n] = e;
}
__global__ void fill_kernel(const int* __restrict__ ei, int e) {
    int i = blockIdx.x * blockDim.x + threadIdx.x;
    if (i < e) {
        int src = ei[i];
        int dst = ei[e + i];
        int pos = atomicAdd(&g_cur[dst], 1);
        g_csr[pos] = src;
    }
}

// ---------------- W prepack: Wp[(k2*2+half)*32 + l] for gemm128 ----------------
__global__ void packW128_kernel(const float* __restrict__ W, ulonglong2* __restrict__ Wp) {
    int i = blockIdx.x * 256 + threadIdx.x;   // < 4096
    int k2 = i >> 6;
    int half_ = (i >> 5) & 1;
    int l = i & 31;
    int c0 = 2 * l + 64 * half_;
    ulonglong2 p;
    p.x = packf2(W[(2 * k2) * 128 + c0], W[(2 * k2 + 1) * 128 + c0]);
    p.y = packf2(W[(2 * k2) * 128 + c0 + 1], W[(2 * k2 + 1) * 128 + c0 + 1]);
    Wp[i] = p;
}

// ---------------- GEMM 128->128 v2: W via L1-resident global, 3 CTAs/SM ------------
// 32 rows/CTA (warp owns 4), lane owns cols {2L,2L+1,2L+64,2L+65}. A tile in smem
// (16KB); packed W read via __ldg (64KB, shared by all CTAs, L1-hot).
__global__ __launch_bounds__(256, 3) void gemm128_kernel(
    const float4* __restrict__ A4, const ulonglong2* __restrict__ Wp,
    const float* __restrict__ asrc, const float* __restrict__ adst,
    __half2* __restrict__ Hh, float* __restrict__ als, float* __restrict__ ald, int n)
{
    __shared__ float4 Asm4[1024];   // 32 rows x 32 float4 = 16KB
    int tid = threadIdx.x;
    int rowbase = blockIdx.x * 32;
    #pragma unroll
    for (int i = tid; i < 1024; i += 256) {
        int row = rowbase + (i >> 5);
        Asm4[i] = (row < n) ? A4[(size_t)row * 32 + (i & 31)]
                            : make_float4(0.f, 0.f, 0.f, 0.f);
    }
    __syncthreads();

    int w = tid >> 5, lane = tid & 31;
    unsigned long long acc[4][4];
    #pragma unroll
    for (int r = 0; r < 4; r++)
        #pragma unroll
        for (int c = 0; c < 4; c++) acc[r][c] = 0ull;

    #pragma unroll 4
    for (int k4 = 0; k4 < 32; k4++) {
        ulonglong2 wa0 = __ldg(&Wp[((2 * k4) * 2 + 0) * 32 + lane]);
        ulonglong2 wb0 = __ldg(&Wp[((2 * k4) * 2 + 1) * 32 + lane]);
        ulonglong2 wa1 = __ldg(&Wp[((2 * k4 + 1) * 2 + 0) * 32 + lane]);
        ulonglong2 wb1 = __ldg(&Wp[((2 * k4 + 1) * 2 + 1) * 32 + lane]);
        #pragma unroll
        for (int r = 0; r < 4; r++) {
            ulonglong2 ap = *(const ulonglong2*)&Asm4[(w * 4 + r) * 32 + k4];
            FMA2(acc[r][0], ap.x, wa0.x);
            FMA2(acc[r][1], ap.x, wa0.y);
            FMA2(acc[r][2], ap.x, wb0.x);
            FMA2(acc[r][3], ap.x, wb0.y);
            FMA2(acc[r][0], ap.y, wa1.x);
            FMA2(acc[r][1], ap.y, wa1.y);
            FMA2(acc[r][2], ap.y, wb1.x);
            FMA2(acc[r][3], ap.y, wb1.y);
        }
    }

    // epilogue: cols {2L,2L+1} (head hA = lane>>4) and {2L+64,2L+65} (head hA+2)
    int c0 = 2 * lane;
    float as0 = asrc[c0], as1 = asrc[c0 + 1], as2_ = asrc[c0 + 64], as3 = asrc[c0 + 65];
    float ad0 = adst[c0], ad1 = adst[c0 + 1], ad2_ = adst[c0 + 64], ad3 = adst[c0 + 65];
    int hA = lane >> 4;
    #pragma unroll
    for (int r = 0; r < 4; r++) {
        int row = rowbase + w * 4 + r;
        if (row >= n) break;
        float v0 = f2lo(acc[r][0]) + f2hi(acc[r][0]);
        float v1 = f2lo(acc[r][1]) + f2hi(acc[r][1]);
        float v2 = f2lo(acc[r][2]) + f2hi(acc[r][2]);
        float v3 = f2lo(acc[r][3]) + f2hi(acc[r][3]);
        Hh[(size_t)row * 64 + lane] = __floats2half2_rn(v0, v1);
        Hh[(size_t)row * 64 + 32 + lane] = __floats2half2_rn(v2, v3);
        float psl = v0 * as0 + v1 * as1;
        float psh = v2 * as2_ + v3 * as3;
        float pdl = v0 * ad0 + v1 * ad1;
        float pdh = v2 * ad2_ + v3 * ad3;
        #pragma unroll
        for (int o = 1; o < 16; o <<= 1) {
            psl += __shfl_xor_sync(0xffffffffu, psl, o);
            psh += __shfl_xor_sync(0xffffffffu, psh, o);
            pdl += __shfl_xor_sync(0xffffffffu, pdl, o);
            pdh += __shfl_xor_sync(0xffffffffu, pdh, o);
        }
        if ((lane & 15) == 0) {
            als[row * 4 + hA] = psl;
            als[row * 4 + hA + 2] = psh;
            ald[row * 4 + hA] = pdl;
            ald[row * 4 + hA + 2] = pdh;
        }
    }
}

// ---------------- GEMM 128->32 (packed f32x2) -> fp16 H + fused logits --------------
__global__ __launch_bounds__(256) void gemm32_kernel(
    const float4* __restrict__ A4, const float* __restrict__ W,
    const float* __restrict__ asrc, const float* __restrict__ adst,
    __half* __restrict__ Hh, float* __restrict__ als, float* __restrict__ ald, int n)
{
    __shared__ unsigned long long Wp[64 * 32];   // 16KB, lane-contiguous
    __shared__ float4 Asm4[2048];                // 32KB
    int tid = threadIdx.x;
    #pragma unroll 2
    for (int i = tid; i < 2048; i += 256) {
        int k2 = i >> 5, l = i & 31;
        Wp[i] = packf2(W[(k2 * 2) * 32 + l], W[(k2 * 2 + 1) * 32 + l]);
    }
    int rowbase = blockIdx.x * 64;
    #pragma unroll 2
    for (int i = tid; i < 2048; i += 256) {
        int row = rowbase + (i >> 5);
        Asm4[i] = (row < n) ? A4[(size_t)row * 32 + (i & 31)]
                            : make_float4(0.f, 0.f, 0.f, 0.f);
    }
    __syncthreads();

    int w = tid >> 5, lane = tid & 31;
    unsigned long long acc[8];
    #pragma unroll
    for (int r = 0; r < 8; r++) acc[r] = 0ull;

    #pragma unroll 4
    for (int k4 = 0; k4 < 32; k4++) {
        unsigned long long w0 = Wp[(2 * k4) * 32 + lane];
        unsigned long long w1 = Wp[(2 * k4 + 1) * 32 + lane];
        #pragma unroll
        for (int r = 0; r < 8; r++) {
            ulonglong2 ap = *(const ulonglong2*)&Asm4[(w * 8 + r) * 32 + k4];
            FMA2(acc[r], ap.x, w0);
            FMA2(acc[r], ap.y, w1);
        }
    }

    float asl = asrc[lane], adl = adst[lane];
    #pragma unroll
    for (int r = 0; r < 8; r++) {
        int row = rowbase + w * 8 + r;
        if (row >= n) break;
        float v = f2lo(acc[r]) + f2hi(acc[r]);
        Hh[(size_t)row * 32 + lane] = __float2half_rn(v);
        float ps = v * asl;
        float pd = v * adl;
        #pragma unroll
        for (int o = 1; o < 32; o <<= 1) {
            ps += __shfl_xor_sync(0xffffffffu, ps, o);
            pd += __shfl_xor_sync(0xffffffffu, pd, o);
        }
        if (lane == 0) { als[row] = ps; ald[row] = pd; }
    }
}

// ---------------- aggregation 4 heads x 32ch, fp16 H gathers, unroll-4 --------------
__global__ __launch_bounds__(256) void agg128_kernel(
    const uint2* __restrict__ Hh, const float* __restrict__ als,
    const float* __restrict__ ald,
    const float* __restrict__ bias, const float* __restrict__ gamma,
    const float* __restrict__ beta, const float* __restrict__ mean,
    const float* __restrict__ var,
    float4* __restrict__ out4, int n)
{
    int v = (blockIdx.x * blockDim.x + threadIdx.x) >> 5;
    if (v >= n) return;
    int lane = threadIdx.x & 31;
    int head = lane >> 3;
    float aldv = __ldg(&ald[v * 4 + head]);
    int s0 = g_off[v], s1 = g_off[v + 1];
    float s = 0.f;
    float4 acc = make_float4(0.f, 0.f, 0.f, 0.f);

    int idx = s0;
    for (; idx + 4 <= s1; idx += 4) {
        int u0 = __ldg(&g_csr[idx]);
        int u1 = __ldg(&g_csr[idx + 1]);
        int u2 = __ldg(&g_csr[idx + 2]);
        int u3 = __ldg(&g_csr[idx + 3]);
        float e0 = __ldg(&als[u0 * 4 + head]) + aldv;
        float e1 = __ldg(&als[u1 * 4 + head]) + aldv;
        float e2 = __ldg(&als[u2 * 4 + head]) + aldv;
        float e3 = __ldg(&als[u3 * 4 + head]) + aldv;
        uint2 p0 = __ldg(&Hh[(size_t)u0 * 32 + lane]);
        uint2 p1 = __ldg(&Hh[(size_t)u1 * 32 + lane]);
        uint2 p2 = __ldg(&Hh[(size_t)u2 * 32 + lane]);
        uint2 p3 = __ldg(&Hh[(size_t)u3 * 32 + lane]);
        float w0 = __expf(lrelu(e0));
        float w1 = __expf(lrelu(e1));
        float w2 = __expf(lrelu(e2));
        float w3 = __expf(lrelu(e3));
        s += (w0 + w1) + (w2 + w3);
        float2 a0 = __half22float2(*(__half2*)&p0.x), b0 = __half22float2(*(__half2*)&p0.y);
        float2 a1 = __half22float2(*(__half2*)&p1.x), b1 = __half22float2(*(__half2*)&p1.y);
        float2 a2 = __half22float2(*(__half2*)&p2.x), b2 = __half22float2(*(__half2*)&p2.y);
        float2 a3 = __half22float2(*(__half2*)&p3.x), b3 = __half22float2(*(__half2*)&p3.y);
        acc.x += w0 * a0.x + w1 * a1.x + w2 * a2.x + w3 * a3.x;
        acc.y += w0 * a0.y + w1 * a1.y + w2 * a2.y + w3 * a3.y;
        acc.z += w0 * b0.x + w1 * b1.x + w2 * b2.x + w3 * b3.x;
        acc.w += w0 * b0.y + w1 * b1.y + w2 * b2.y + w3 * b3.y;
    }
    for (; idx < s1; idx++) {
        int u = __ldg(&g_csr[idx]);
        float wt = __expf(lrelu(__ldg(&als[u * 4 + head]) + aldv));
        uint2 p = __ldg(&Hh[(size_t)u * 32 + lane]);
        float2 a = __half22float2(*(__half2*)&p.x), b = __half22float2(*(__half2*)&p.y);
        s += wt;
        acc.x += wt * a.x;
        acc.y += wt * a.y;
        acc.z += wt * b.x;
        acc.w += wt * b.y;
    }

    float inv = 1.f / (s + 1e-16f);
    float4 bi = ((const float4*)bias)[lane];
    float4 mn = ((const float4*)mean)[lane];
    float4 vr = ((const float4*)var)[lane];
    float4 gm = ((const float4*)gamma)[lane];
    float4 bt = ((const float4*)beta)[lane];
    float4 y;
    y.x = (acc.x * inv + bi.x - mn.x) * rsqrtf(vr.x + 1e-5f) * gm.x + bt.x;
    y.y = (acc.y * inv + bi.y - mn.y) * rsqrtf(vr.y + 1e-5f) * gm.y + bt.y;
    y.z = (acc.z * inv + bi.z - mn.z) * rsqrtf(vr.z + 1e-5f) * gm.z + bt.z;
    y.w = (acc.w * inv + bi.w - mn.w) * rsqrtf(vr.w + 1e-5f) * gm.w + bt.w;
    y.x = y.x > 0.f ? y.x : expm1f(y.x);
    y.y = y.y > 0.f ? y.y : expm1f(y.y);
    y.z = y.z > 0.f ? y.z : expm1f(y.z);
    y.w = y.w > 0.f ? y.w : expm1f(y.w);
    out4[(size_t)v * 32 + lane] = y;
}

// ---------------- layer-2 aggregation (1 head, fp16 H) + BN + ELU + classifier ------
__global__ __launch_bounds__(256) void agg32_kernel(
    const __half* __restrict__ H, const float* __restrict__ als,
    const float* __restrict__ ald,
    const float* __restrict__ bias, const float* __restrict__ gamma,
    const float* __restrict__ beta, const float* __restrict__ mean,
    const float* __restrict__ var,
    const float* __restrict__ Wc, const float* __restrict__ bc,
    float* __restrict__ out, int n)
{
    int v = (blockIdx.x * blockDim.x + threadIdx.x) >> 5;
    if (v >= n) return;
    int lane = threadIdx.x & 31;
    float aldv = __ldg(&ald[v]);
    int s0 = g_off[v], s1 = g_off[v + 1];
    float s = 0.f, acc = 0.f;

    int idx = s0;
    for (; idx + 4 <= s1; idx += 4) {
        int u0 = __ldg(&g_csr[idx]);
        int u1 = __ldg(&g_csr[idx + 1]);
        int u2 = __ldg(&g_csr[idx + 2]);
        int u3 = __ldg(&g_csr[idx + 3]);
        float e0 = __ldg(&als[u0]) + aldv;
        float e1 = __ldg(&als[u1]) + aldv;
        float e2 = __ldg(&als[u2]) + aldv;
        float e3 = __ldg(&als[u3]) + aldv;
        float h0 = __half2float(__ldg(&H[(size_t)u0 * 32 + lane]));
        float h1 = __half2float(__ldg(&H[(size_t)u1 * 32 + lane]));
        float h2 = __half2float(__ldg(&H[(size_t)u2 * 32 + lane]));
        float h3 = __half2float(__ldg(&H[(size_t)u3 * 32 + lane]));
        float w0 = __expf(lrelu(e0));
        float w1 = __expf(lrelu(e1));
        float w2 = __expf(lrelu(e2));
        float w3 = __expf(lrelu(e3));
        s += (w0 + w1) + (w2 + w3);
        acc += w0 * h0 + w1 * h1 + w2 * h2 + w3 * h3;
    }
    for (; idx < s1; idx++) {
        int u = __ldg(&g_csr[idx]);
        float wt = __expf(lrelu(__ldg(&als[u]) + aldv));
        s += wt;
        acc += wt * __half2float(__ldg(&H[(size_t)u * 32 + lane]));
    }

    float y = acc / (s + 1e-16f) + bias[lane];
    y = (y - mean[lane]) * rsqrtf(var[lane] + 1e-5f) * gamma[lane] + beta[lane];
    y = y > 0.f ? y : expm1f(y);
    #pragma unroll
    for (int cc = 0; cc < 10; cc++) {
        float p = y * Wc[lane * 10 + cc];
        #pragma unroll
        for (int o = 16; o; o >>= 1) p += __shfl_xor_sync(0xffffffffu, p, o);
        if (lane == 0) out[(size_t)v * 10 + cc] = p + bc[cc];
    }
}

// ---------------- launch ----------------
extern "C" void kernel_launch(void* const* d_in, const int* in_sizes, int n_in,
                              void* d_out, int out_size) {
    const float* x   = (const float*)d_in[0];
    const int*   ei  = (const int*)d_in[1];
    const float* W0  = (const float*)d_in[2];
    const float* as0 = (const float*)d_in[3];
    const float* ad0 = (const float*)d_in[4];
    const float* b0  = (const float*)d_in[5];
    const float* gm0 = (const float*)d_in[6];
    const float* bt0 = (const float*)d_in[7];
    const float* m0  = (const float*)d_in[8];
    const float* v0  = (const float*)d_in[9];
    const float* W1  = (const float*)d_in[10];
    const float* as1 = (const float*)d_in[11];
    const float* ad1 = (const float*)d_in[12];
    const float* b1  = (const float*)d_in[13];
    const float* gm1 = (const float*)d_in[14];
    const float* bt1 = (const float*)d_in[15];
    const float* m1  = (const float*)d_in[16];
    const float* v1  = (const float*)d_in[17];
    const float* W2  = (const float*)d_in[18];
    const float* as2 = (const float*)d_in[19];
    const float* ad2 = (const float*)d_in[20];
    const float* b2  = (const float*)d_in[21];
    const float* gm2 = (const float*)d_in[22];
    const float* bt2 = (const float*)d_in[23];
    const float* m2  = (const float*)d_in[24];
    const float* v2  = (const float*)d_in[25];
    const float* Wc  = (const float*)d_in[26];
    const float* bc  = (const float*)d_in[27];

    int n = in_sizes[0] / 128;   // 100000
    int e = in_sizes[1] / 2;     // 1600000

    float *feat, *als, *ald;
    __half *hh, *h2;
    ulonglong2 *wp0, *wp1;
    cudaGetSymbolAddress((void**)&feat, g_feat);
    cudaGetSymbolAddress((void**)&hh, g_hh);
    cudaGetSymbolAddress((void**)&h2, g_h2);
    cudaGetSymbolAddress((void**)&als, g_als);
    cudaGetSymbolAddress((void**)&ald, g_ald);
    cudaGetSymbolAddress((void**)&wp0, g_Wp0);
    cudaGetSymbolAddress((void**)&wp1, g_Wp1);

    // side stream + fork/join events (created once; host-side resources only)
    static cudaStream_t s2 = nullptr;
    static cudaEvent_t evFork = nullptr, evCsr = nullptr;
    if (!s2) {
        cudaStreamCreateWithFlags(&s2, cudaStreamNonBlocking);
        cudaEventCreateWithFlags(&evFork, cudaEventDisableTiming);
        cudaEventCreateWithFlags(&evCsr, cudaEventDisableTiming);
    }

    int nb = (n + 1023) / 1024;
    int eb = (e + 255) / 256;
    int g128_blocks = (n + 31) / 32;
    int g32_blocks = (n + 63) / 64;
    int agg_blocks = (n + 7) / 8;

    // fork: CSR build on s2, overlapped with W prepack + layer-0 GEMM on main stream
    cudaEventRecord(evFork, 0);
    cudaStreamWaitEvent(s2, evFork, 0);

    zero_deg_kernel<<<(n + 255) / 256, 256, 0, s2>>>(n);
    count_kernel<<<eb, 256, 0, s2>>>(ei, e);
    scan1_kernel<<<nb, 1024, 0, s2>>>(n);
    scan2_kernel<<<1, 128, 0, s2>>>(nb);
    scan3_kernel<<<nb, 1024, 0, s2>>>(n, e);
    fill_kernel<<<eb, 256, 0, s2>>>(ei, e);
    cudaEventRecord(evCsr, s2);

    // main stream: prepack W0/W1, then layer-0 GEMM (no CSR dependency)
    packW128_kernel<<<16, 256>>>(W0, wp0);
    packW128_kernel<<<16, 256>>>(W1, wp1);
    gemm128_kernel<<<g128_blocks, 256>>>(
        (const float4*)x, wp0, as0, ad0, (__half2*)hh, als, ald, n);

    // join: aggregation needs both the GEMM and the CSR
    cudaStreamWaitEvent(0, evCsr, 0);

    // layer 0 aggregation
    agg128_kernel<<<agg_blocks, 256>>>(
        (const uint2*)hh, als, ald, b0, gm0, bt0, m0, v0, (float4*)feat, n);

    // layer 1
    gemm128_kernel<<<g128_blocks, 256>>>(
        (const float4*)feat, wp1, as1, ad1, (__half2*)hh, als, ald, n);
    agg128_kernel<<<agg_blocks, 256>>>(
        (const uint2*)hh, als, ald, b1, gm1, bt1, m1, v1, (float4*)feat, n);

    // layer 2 (single head, fp16 H) + classifier
    gemm32_kernel<<<g32_blocks, 256>>>(
        (const float4*)feat, W2, as2, ad2, h2, als, ald, n);
    agg32_kernel<<<agg_blocks, 256>>>(
        h2, als, ald, b2, gm2, bt2, m2, v2, Wc, bc, (float*)d_out, n);
}